// round 16
// baseline (speedup 1.0000x reference)
#include <cuda_runtime.h>
#include <cuda_bf16.h>
#include <cstdint>

#define Bsz 128
#define Tsz 512
#define Isz 64
#define Hsz 256
#define Gsz 768   // 3*H

// ---- device scratch (no cudaMalloc allowed) --------------------------------
__device__ float    g_gx  [(size_t)Tsz * Bsz * Gsz];  // [t][b][768] gate preactivations
__device__ float    g_hbuf[2 * Bsz * Hsz];            // double-buffered hidden state
__device__ unsigned g_cnt [2 * Tsz * 8];              // per layer/step/batch-group barrier

// ---- zero hidden state (+ optionally barrier counters) ---------------------
__global__ void zero_state(int zero_cnt) {
    const int stride = gridDim.x * blockDim.x;
    const int i0 = blockIdx.x * blockDim.x + threadIdx.x;
    for (int i = i0; i < 2 * Bsz * Hsz; i += stride) g_hbuf[i] = 0.0f;
    if (zero_cnt)
        for (int i = i0; i < 2 * Tsz * 8; i += stride) g_cnt[i] = 0u;
}

// ---- shared helpers: bf16 split + mma/ldmatrix -----------------------------
#define AKU 12   // uints per 16-row block row (8 data + 4 pad) -> LDSM conflict-free

__device__ __forceinline__ unsigned pack2bf(float f0, float f1, float& r0, float& r1) {
    __nv_bfloat16 h0 = __float2bfloat16(f0);
    __nv_bfloat16 h1 = __float2bfloat16(f1);
    r0 = f0 - __bfloat162float(h0);
    r1 = f1 - __bfloat162float(h1);
    return (unsigned)__bfloat16_as_ushort(h0) |
           ((unsigned)__bfloat16_as_ushort(h1) << 16);
}
__device__ __forceinline__ unsigned pack2bf_only(float f0, float f1) {
    __nv_bfloat16 h0 = __float2bfloat16(f0);
    __nv_bfloat16 h1 = __float2bfloat16(f1);
    return (unsigned)__bfloat16_as_ushort(h0) |
           ((unsigned)__bfloat16_as_ushort(h1) << 16);
}

#define LDSM_X4(r0, r1, r2, r3, addr)                                         \
    asm volatile("ldmatrix.sync.aligned.m8n8.x4.shared.b16 {%0,%1,%2,%3}, [%4];" \
        : "=r"(r0), "=r"(r1), "=r"(r2), "=r"(r3) : "r"(addr))

#define MMA_BF16(c, a, b)                                                     \
    asm volatile(                                                             \
        "mma.sync.aligned.m16n8k16.row.col.f32.bf16.bf16.f32 "                \
        "{%0,%1,%2,%3},{%4,%5,%6,%7},{%8,%9},{%0,%1,%2,%3};"                  \
        : "+f"((c)[0]), "+f"((c)[1]), "+f"((c)[2]), "+f"((c)[3])              \
        : "r"((a)[0]), "r"((a)[1]), "r"((a)[2]), "r"((a)[3]),                 \
          "r"((b)[0]), "r"((b)[1]))

// ---- bf16x2-split tensor-core GEMM (NT), CTA 128x64 (R13-proven) -----------
// g_gx[m][n] = A(m,:)·W(n,:) + bias[n];  Arow(m)=x[(b*T+t)*I], m=t*128+b, K=64
__global__ __launch_bounds__(256) void gemm_bf16x2(
    const float* __restrict__ A, const float* __restrict__ W,
    const float* __restrict__ bias, int K)
{
    __shared__ unsigned gsm[2*128*AKU*2 + 2*64*AKU*2];
    unsigned* sAh = gsm;
    unsigned* sAl = gsm + 2*128*AKU;
    unsigned* sBh = gsm + 4*128*AKU;
    unsigned* sBl = gsm + 4*128*AKU + 2*64*AKU;

    const int tid  = threadIdx.x;
    const int warp = tid >> 5, lane = tid & 31;
    const int gr   = lane >> 2, tg = lane & 3;
    const int wm   = warp & 3,  wn = warp >> 2;
    const int bm   = blockIdx.y, bn = blockIdx.x;

    int arow[4], ac4[4], brow[2], bc4[2];
    const float* asrc[4];
    const float* bsrc[2];
#pragma unroll
    for (int i = 0; i < 4; ++i) {
        const int idx = tid + (i << 8);
        arow[i] = idx >> 3; ac4[i] = idx & 7;
        asrc[i] = A + ((size_t)arow[i] * Tsz + bm) * Isz + (ac4[i] << 2);
    }
#pragma unroll
    for (int i = 0; i < 2; ++i) {
        const int idx = tid + (i << 8);
        brow[i] = idx >> 3; bc4[i] = idx & 7;
        bsrc[i] = W + ((size_t)(bn * 64 + brow[i])) * K + (bc4[i] << 2);
    }

    float c[2][4][4];
#pragma unroll
    for (int ms = 0; ms < 2; ++ms)
#pragma unroll
        for (int ns = 0; ns < 4; ++ns)
#pragma unroll
            for (int i = 0; i < 4; ++i) c[ms][ns][i] = 0.0f;

    const int lrow = lane & 15, lkh = lane >> 4;
    unsigned aAh = (unsigned)__cvta_generic_to_shared(sAh);
    unsigned aAl = (unsigned)__cvta_generic_to_shared(sAl);

    float4 ra[4], rb[2];
#pragma unroll
    for (int i = 0; i < 4; ++i) ra[i] = __ldg((const float4*)asrc[i]);
#pragma unroll
    for (int i = 0; i < 2; ++i) rb[i] = __ldg((const float4*)bsrc[i]);

    for (int kc = 0; kc < K; kc += 32) {
#pragma unroll
        for (int i = 0; i < 4; ++i) {
            const int ks = ac4[i] >> 2, pc = (ac4[i] & 3) << 1;
            const int di = ((ks << 7) + arow[i]) * AKU + pc;
            float r0, r1, r2, r3;
            sAh[di]     = pack2bf(ra[i].x, ra[i].y, r0, r1);
            sAh[di + 1] = pack2bf(ra[i].z, ra[i].w, r2, r3);
            sAl[di]     = pack2bf_only(r0, r1);
            sAl[di + 1] = pack2bf_only(r2, r3);
        }
#pragma unroll
        for (int i = 0; i < 2; ++i) {
            const int ks = bc4[i] >> 2, pc = (bc4[i] & 3) << 1;
            const int di = ((ks << 6) + brow[i]) * AKU + pc;
            float r0, r1, r2, r3;
            sBh[di]     = pack2bf(rb[i].x, rb[i].y, r0, r1);
            sBh[di + 1] = pack2bf(rb[i].z, rb[i].w, r2, r3);
            sBl[di]     = pack2bf_only(r0, r1);
            sBl[di + 1] = pack2bf_only(r2, r3);
        }
        __syncthreads();

        if (kc + 32 < K) {
#pragma unroll
            for (int i = 0; i < 4; ++i)
                ra[i] = __ldg((const float4*)(asrc[i] + kc + 32));
#pragma unroll
            for (int i = 0; i < 2; ++i)
                rb[i] = __ldg((const float4*)(bsrc[i] + kc + 32));
        }

#pragma unroll
        for (int ks = 0; ks < 2; ++ks) {
            unsigned Ah[2][4], Al[2][4];
#pragma unroll
            for (int ms = 0; ms < 2; ++ms) {
                const int rbase = wm * 32 + ms * 16;
                const unsigned off =
                    ((unsigned)(((ks << 7) + rbase + lrow) * AKU + (lkh << 2))) << 2;
                LDSM_X4(Ah[ms][0], Ah[ms][1], Ah[ms][2], Ah[ms][3], aAh + off);
                LDSM_X4(Al[ms][0], Al[ms][1], Al[ms][2], Al[ms][3], aAl + off);
            }
            unsigned Bh[4][2], Bl[4][2];
#pragma unroll
            for (int ns = 0; ns < 4; ++ns) {
                const int nrow = wn * 32 + ns * 8 + gr;
                const int di = ((ks << 6) + nrow) * AKU;
                Bh[ns][0] = sBh[di + tg];
                Bh[ns][1] = sBh[di + 4 + tg];
                Bl[ns][0] = sBl[di + tg];
                Bl[ns][1] = sBl[di + 4 + tg];
            }
#pragma unroll
            for (int ms = 0; ms < 2; ++ms)
#pragma unroll
                for (int ns = 0; ns < 4; ++ns)
                    MMA_BF16(c[ms][ns], Ah[ms], Bh[ns]);
#pragma unroll
            for (int ms = 0; ms < 2; ++ms)
#pragma unroll
                for (int ns = 0; ns < 4; ++ns)
                    MMA_BF16(c[ms][ns], Ah[ms], Bl[ns]);
#pragma unroll
            for (int ms = 0; ms < 2; ++ms)
#pragma unroll
                for (int ns = 0; ns < 4; ++ns)
                    MMA_BF16(c[ms][ns], Al[ms], Bh[ns]);
        }
        __syncthreads();
    }

#pragma unroll
    for (int ms = 0; ms < 2; ++ms) {
#pragma unroll
        for (int ns = 0; ns < 4; ++ns) {
            const int col = bn * 64 + wn * 32 + ns * 8 + tg * 2;
            const float b0 = __ldg(bias + col);
            const float b1 = __ldg(bias + col + 1);
            const size_t m0 = (size_t)bm * 128 + wm * 32 + ms * 16 + gr;
            float2 v0 = make_float2(c[ms][ns][0] + b0, c[ms][ns][1] + b1);
            float2 v1 = make_float2(c[ms][ns][2] + b0, c[ms][ns][3] + b1);
            *(float2*)(g_gx + m0 * Gsz + col)       = v0;
            *(float2*)(g_gx + (m0 + 8) * Gsz + col) = v1;
        }
    }
}

// ---- tensor-core GRU scan with fused next-layer input GEMM -----------------
// 128 CTAs = 8 bg x 16 hg; CTA tile: 16 batch x 16 hidden x 3 gates.
// fuse=1: at iteration t>=1 the staged h == y(t-1); run a second 3-term MMA
// set vs W_ih(next) (pre-split in smem) and store gx_next[t-1] into g_gx
// (this CTA consumed that slot at iteration t-2). Tail t==Tsz emits gx[511].
// BIAS FIX vs R14: bih_extra's n-component adds to gx_n (outside r), never bhn.
#define SP_STRIDE 49
#define SW_SLOT   52
#define SCAN3_WORDS (2*16*16*AKU + 256*SW_SLOT + 2*8*16*SP_STRIDE + 16*17)
#define SCAN3_BYTES (SCAN3_WORDS * 4)

__global__ __launch_bounds__(256, 1) void gru_scan_mma(
    const float* __restrict__ Whh, const float* __restrict__ bhh,
    const float* __restrict__ bih_extra, const float* __restrict__ Wnext,
    int layer, int fuse)
{
    extern __shared__ unsigned smu[];
    unsigned* sAh = smu;                          // [16 ks][16 row][12]
    unsigned* sAl = smu + 16*16*AKU;
    unsigned* sW  = smu + 2*16*16*AKU;            // [256 threads][52]
    float* sp     = (float*)(sW + 256*SW_SLOT);   // [8][16][49]
    float* sp2    = sp + 8*16*SP_STRIDE;          // [8][16][49]
    float* sHold  = sp2 + 8*16*SP_STRIDE;         // [16][17]

    const int tid  = threadIdx.x;
    const int warp = tid >> 5, lane = tid & 31;
    const int gr   = lane >> 2, tg = lane & 3;
    const int bg   = blockIdx.x >> 4;             // 0..7
    const int hg   = blockIdx.x & 15;             // 0..15
    const int b0   = bg << 4, j0 = hg << 4;
    const int bl   = tid >> 4;                    // epilogue batch 0..15
    const int jl   = tid & 15;                    // epilogue hidden 0..15

    // recurrent B fragments (weights) -> registers, once
    unsigned Bh[2][6][2], Bl[2][6][2];
#pragma unroll
    for (int s = 0; s < 2; ++s) {
#pragma unroll
        for (int ns = 0; ns < 6; ++ns) {
            const int n = ns * 8 + gr;
            const int g = n >> 4, jj = n & 15;
            const float* wr = Whh + (size_t)(g * 256 + j0 + jj) * 256;
            const int k0 = warp * 32 + s * 16 + tg * 2;
            float r0, r1;
            Bh[s][ns][0] = pack2bf(wr[k0],     wr[k0 + 1], r0, r1);
            Bl[s][ns][0] = pack2bf_only(r0, r1);
            Bh[s][ns][1] = pack2bf(wr[k0 + 8], wr[k0 + 9], r0, r1);
            Bl[s][ns][1] = pack2bf_only(r0, r1);
        }
    }
    // fused B fragments (W_ih next) -> smem, once
    if (fuse) {
        const int base = (warp * 32 + lane) * SW_SLOT;
#pragma unroll
        for (int s = 0; s < 2; ++s) {
#pragma unroll
            for (int ns = 0; ns < 6; ++ns) {
                const int n = ns * 8 + gr;
                const int g = n >> 4, jj = n & 15;
                const float* wr = Wnext + (size_t)(g * 256 + j0 + jj) * 256;
                const int k0 = warp * 32 + s * 16 + tg * 2;
                float r0, r1;
                unsigned h0 = pack2bf(wr[k0],     wr[k0 + 1], r0, r1);
                unsigned l0 = pack2bf_only(r0, r1);
                unsigned h1 = pack2bf(wr[k0 + 8], wr[k0 + 9], r0, r1);
                unsigned l1 = pack2bf_only(r0, r1);
                const int di = base + (s * 6 + ns) * 4;
                sW[di] = h0; sW[di + 1] = h1; sW[di + 2] = l0; sW[di + 3] = l1;
            }
        }
    }
    const float bhr = bhh[j0 + jl];
    const float bhz = bhh[256 + j0 + jl];
    const float bhn = bhh[512 + j0 + jl];
    // b_ih of THIS layer (when gx lacks it): r/z go in the sums; n goes with gx_n
    float bxr = 0.f, bxz = 0.f, bxn = 0.f;
    if (bih_extra) {
        bxr = bih_extra[j0 + jl];
        bxz = bih_extra[256 + j0 + jl];
        bxn = bih_extra[512 + j0 + jl];
    }
    unsigned* cnt = g_cnt + layer * (Tsz * 8);

    // gx prefetch (one (b,j) per thread, 3 gates)
    const float* gxp = g_gx + (size_t)(b0 + bl) * Gsz + j0 + jl;
    const size_t gxstep = (size_t)128 * Gsz;
    float gxr = __ldcg(gxp);
    float gxz = __ldcg(gxp + 256);
    float gxn = __ldcg(gxp + 512);

    const int lrow = lane & 15, lkh = lane >> 4;
    const unsigned aAh = (unsigned)__cvta_generic_to_shared(sAh);
    const unsigned aAl = (unsigned)__cvta_generic_to_shared(sAl);
    const int swbase = (warp * 32 + lane) * SW_SLOT;

    const int tEnd = Tsz + (fuse ? 1 : 0);
    int cur = 0;
    for (int t = 0; t < tEnd; ++t) {
        if (t > 0) {
            const unsigned* c = cnt + ((t - 1) << 3) + bg;
            unsigned v;
            do {
                asm volatile("ld.acquire.gpu.global.u32 %0, [%1];"
                             : "=r"(v) : "l"(c) : "memory");
            } while (v < 16u);
        }
        // stage h: 16 rows x 256 -> bf16 hi/lo planes (ldmatrix layout)
        const float* hsrc = g_hbuf + cur * (Bsz * Hsz) + (b0 << 8);
#pragma unroll
        for (int r = 0; r < 4; ++r) {
            const int idx = tid + (r << 8);
            const int row = idx >> 6, f4 = idx & 63;
            float4 v = __ldcg((const float4*)(hsrc + (row << 8)) + f4);
            const int ks = f4 >> 2, pc = (f4 & 3) << 1;
            const int di = ((ks << 4) + row) * AKU + pc;
            float r0, r1, r2, r3;
            sAh[di]     = pack2bf(v.x, v.y, r0, r1);
            sAh[di + 1] = pack2bf(v.z, v.w, r2, r3);
            sAl[di]     = pack2bf_only(r0, r1);
            sAl[di + 1] = pack2bf_only(r2, r3);
        }
        sHold[bl * 17 + jl] = __ldcg(hsrc + (bl << 8) + j0 + jl);
        __syncthreads();

        const bool do_fused = fuse && (t >= 1);
        float c2[6][4];
        if (do_fused) {
#pragma unroll
            for (int ns = 0; ns < 6; ++ns)
#pragma unroll
                for (int i = 0; i < 4; ++i) c2[ns][i] = 0.0f;
        }

        if (t < Tsz) {
            float c[6][4];
#pragma unroll
            for (int ns = 0; ns < 6; ++ns)
#pragma unroll
                for (int i = 0; i < 4; ++i) c[ns][i] = 0.0f;

#pragma unroll
            for (int s = 0; s < 2; ++s) {
                const int ksg = warp * 2 + s;
                const unsigned off =
                    ((unsigned)(((ksg << 4) + lrow) * AKU + (lkh << 2))) << 2;
                unsigned Ah[4], Al[4];
                LDSM_X4(Ah[0], Ah[1], Ah[2], Ah[3], aAh + off);
                LDSM_X4(Al[0], Al[1], Al[2], Al[3], aAl + off);
#pragma unroll
                for (int ns = 0; ns < 6; ++ns) MMA_BF16(c[ns], Ah, Bh[s][ns]);
#pragma unroll
                for (int ns = 0; ns < 6; ++ns) MMA_BF16(c[ns], Ah, Bl[s][ns]);
#pragma unroll
                for (int ns = 0; ns < 6; ++ns) MMA_BF16(c[ns], Al, Bh[s][ns]);
                if (do_fused) {
#pragma unroll
                    for (int ns = 0; ns < 6; ++ns) {
                        const uint4 q = *(const uint4*)(sW + swbase + (s * 6 + ns) * 4);
                        unsigned bh2[2] = {q.x, q.y};
                        unsigned bl2[2] = {q.z, q.w};
                        MMA_BF16(c2[ns], Ah, bh2);
                        MMA_BF16(c2[ns], Ah, bl2);
                        MMA_BF16(c2[ns], Al, bh2);
                    }
                }
            }
            float* spw = sp + warp * (16 * SP_STRIDE);
#pragma unroll
            for (int ns = 0; ns < 6; ++ns) {
                const int n = ns * 8 + tg * 2;
                spw[gr * SP_STRIDE + n]           = c[ns][0];
                spw[gr * SP_STRIDE + n + 1]       = c[ns][1];
                spw[(gr + 8) * SP_STRIDE + n]     = c[ns][2];
                spw[(gr + 8) * SP_STRIDE + n + 1] = c[ns][3];
            }
        } else {
            // tail: fused MMAs only (staged h == y(Tsz-1))
#pragma unroll
            for (int s = 0; s < 2; ++s) {
                const int ksg = warp * 2 + s;
                const unsigned off =
                    ((unsigned)(((ksg << 4) + lrow) * AKU + (lkh << 2))) << 2;
                unsigned Ah[4], Al[4];
                LDSM_X4(Ah[0], Ah[1], Ah[2], Ah[3], aAh + off);
                LDSM_X4(Al[0], Al[1], Al[2], Al[3], aAl + off);
#pragma unroll
                for (int ns = 0; ns < 6; ++ns) {
                    const uint4 q = *(const uint4*)(sW + swbase + (s * 6 + ns) * 4);
                    unsigned bh2[2] = {q.x, q.y};
                    unsigned bl2[2] = {q.z, q.w};
                    MMA_BF16(c2[ns], Ah, bh2);
                    MMA_BF16(c2[ns], Ah, bl2);
                    MMA_BF16(c2[ns], Al, bh2);
                }
            }
        }
        if (do_fused) {
            float* spw2 = sp2 + warp * (16 * SP_STRIDE);
#pragma unroll
            for (int ns = 0; ns < 6; ++ns) {
                const int n = ns * 8 + tg * 2;
                spw2[gr * SP_STRIDE + n]           = c2[ns][0];
                spw2[gr * SP_STRIDE + n + 1]       = c2[ns][1];
                spw2[(gr + 8) * SP_STRIDE + n]     = c2[ns][2];
                spw2[(gr + 8) * SP_STRIDE + n + 1] = c2[ns][3];
            }
        }
        __syncthreads();

        if (t < Tsz) {
            float ar = bhr + bxr + gxr, az = bhz + bxz + gxz, an = bhn;
#pragma unroll
            for (int w8 = 0; w8 < 8; ++w8) {
                const float* q = sp + w8 * (16 * SP_STRIDE) + bl * SP_STRIDE;
                ar += q[jl];
                az += q[16 + jl];
                an += q[32 + jl];
            }
            const float r = __fdividef(1.0f, 1.0f + __expf(-ar));
            const float z = __fdividef(1.0f, 1.0f + __expf(-az));
            // BIAS FIX: b_ih_n stays OUTSIDE the r* factor
            const float xn = fmaf(r, an, gxn + bxn);
            const float e = __expf(2.0f * fabsf(xn));
            float n = 1.0f - __fdividef(2.0f, e + 1.0f);
            n = copysignf(n, xn);

            const float hold = sHold[bl * 17 + jl];
            const float hnew = fmaf(z, hold - n, n);   // (1-z)*n + z*h

            __stcg(g_hbuf + (cur ^ 1) * (Bsz * Hsz) + ((b0 + bl) << 8) + j0 + jl,
                   hnew);

            if (t + 1 < Tsz) {
                const float* p = gxp + (size_t)(t + 1) * gxstep;
                gxr = __ldcg(p);
                gxz = __ldcg(p + 256);
                gxn = __ldcg(p + 512);
            }
        }
        if (do_fused) {
            float ar2 = 0.f, az2 = 0.f, an2 = 0.f;
#pragma unroll
            for (int w8 = 0; w8 < 8; ++w8) {
                const float* q = sp2 + w8 * (16 * SP_STRIDE) + bl * SP_STRIDE;
                ar2 += q[jl];
                az2 += q[16 + jl];
                an2 += q[32 + jl];
            }
            float* gdst = g_gx + ((size_t)(((t - 1) << 7) + b0 + bl)) * Gsz
                          + j0 + jl;
            __stcg(gdst,       ar2);
            __stcg(gdst + 256, az2);
            __stcg(gdst + 512, an2);
        }

        __syncthreads();   // smem reads done; hnew stores issued
        if (((t + 1 < Tsz) || (fuse && t < Tsz)) && tid == 0) {
            asm volatile("red.release.gpu.global.add.u32 [%0], 1;"
                         :: "l"(cnt + (t << 3) + bg) : "memory");
        }
        cur ^= 1;
    }
}

// ---- head: out[b] = W2 . relu(W1 . h_last[b] + b1) + b2 --------------------
__global__ void head_kernel(const float* __restrict__ W1, const float* __restrict__ b1,
                            const float* __restrict__ W2, const float* __restrict__ b2,
                            float* __restrict__ out)
{
    __shared__ float red[128];
    const int b = blockIdx.x, u = threadIdx.x;
    const float* hb = g_hbuf + (b << 8);
    const float* w  = W1 + (size_t)u * 256;

    float acc = b1[u];
#pragma unroll 8
    for (int k4 = 0; k4 < 64; ++k4) {
        const float4 h4 = __ldcg((const float4*)hb + k4);
        const float4 w4 = __ldg((const float4*)w + k4);
        acc = fmaf(h4.x, w4.x, acc); acc = fmaf(h4.y, w4.y, acc);
        acc = fmaf(h4.z, w4.z, acc); acc = fmaf(h4.w, w4.w, acc);
    }
    red[u] = fmaxf(acc, 0.0f) * __ldg(W2 + u);
    __syncthreads();
#pragma unroll
    for (int s = 64; s > 0; s >>= 1) {
        if (u < s) red[u] += red[u + s];
        __syncthreads();
    }
    if (u == 0) out[b] = red[0] + b2[0];
}

// ---- launch sequence (graph-capturable: kernel launches only) --------------
extern "C" void kernel_launch(void* const* d_in, const int* in_sizes, int n_in,
                              void* d_out, int out_size)
{
    const float* x    = (const float*)d_in[0];
    const float* Wih0 = (const float*)d_in[1];
    const float* Whh0 = (const float*)d_in[2];
    const float* bih0 = (const float*)d_in[3];
    const float* bhh0 = (const float*)d_in[4];
    const float* Wih1 = (const float*)d_in[5];
    const float* Whh1 = (const float*)d_in[6];
    const float* bih1 = (const float*)d_in[7];
    const float* bhh1 = (const float*)d_in[8];
    const float* W1   = (const float*)d_in[9];
    const float* b1   = (const float*)d_in[10];
    const float* W2   = (const float*)d_in[11];
    const float* b2   = (const float*)d_in[12];
    float* out = (float*)d_out;

    cudaFuncSetAttribute(gru_scan_mma, cudaFuncAttributeMaxDynamicSharedMemorySize,
                         SCAN3_BYTES);

    const dim3 ggrid(12, 512);

    // fresh state + barrier counters every replay
    zero_state<<<64, 256>>>(1);

    // layer 0: input GEMM, then scan with fused layer-1 input GEMM
    gemm_bf16x2<<<ggrid, 256>>>(x, Wih0, bih0, Isz);
    gru_scan_mma<<<128, 256, SCAN3_BYTES>>>(Whh0, bhh0, nullptr, Wih1, 0, 1);

    // layer 1: re-zero hidden state, scan (gx in g_gx lacks bih1 -> bih_extra)
    zero_state<<<64, 256>>>(0);
    gru_scan_mma<<<128, 256, SCAN3_BYTES>>>(Whh1, bhh1, bih1, nullptr, 1, 0);

    // head
    head_kernel<<<128, 128>>>(W1, b1, W2, b2, out);
}

// round 17
// speedup vs baseline: 1.1237x; 1.1237x over previous
#include <cuda_runtime.h>
#include <cuda_bf16.h>
#include <cstdint>

#define Bsz 128
#define Tsz 512
#define Isz 64
#define Hsz 256
#define Gsz 768   // 3*H

// ---- device scratch (no cudaMalloc allowed) --------------------------------
__device__ float    g_gx  [(size_t)Tsz * Bsz * Gsz];  // [t][b][768] gate preactivations
__device__ float    g_hbuf[2 * Bsz * Hsz];            // double-buffered hidden state
__device__ unsigned g_cnt [2 * Tsz * 8];              // per layer/step/batch-group barrier

// ---- zero hidden state (+ optionally barrier counters) ---------------------
__global__ void zero_state(int zero_cnt) {
    const int stride = gridDim.x * blockDim.x;
    const int i0 = blockIdx.x * blockDim.x + threadIdx.x;
    for (int i = i0; i < 2 * Bsz * Hsz; i += stride) g_hbuf[i] = 0.0f;
    if (zero_cnt)
        for (int i = i0; i < 2 * Tsz * 8; i += stride) g_cnt[i] = 0u;
}

// ---- shared helpers: bf16 split + mma/ldmatrix -----------------------------
#define AKU 12   // uints per 16-row block row (8 data + 4 pad) -> LDSM conflict-free

__device__ __forceinline__ unsigned pack2bf(float f0, float f1, float& r0, float& r1) {
    __nv_bfloat16 h0 = __float2bfloat16(f0);
    __nv_bfloat16 h1 = __float2bfloat16(f1);
    r0 = f0 - __bfloat162float(h0);
    r1 = f1 - __bfloat162float(h1);
    return (unsigned)__bfloat16_as_ushort(h0) |
           ((unsigned)__bfloat16_as_ushort(h1) << 16);
}
__device__ __forceinline__ unsigned pack2bf_only(float f0, float f1) {
    __nv_bfloat16 h0 = __float2bfloat16(f0);
    __nv_bfloat16 h1 = __float2bfloat16(f1);
    return (unsigned)__bfloat16_as_ushort(h0) |
           ((unsigned)__bfloat16_as_ushort(h1) << 16);
}

#define LDSM_X4(r0, r1, r2, r3, addr)                                         \
    asm volatile("ldmatrix.sync.aligned.m8n8.x4.shared.b16 {%0,%1,%2,%3}, [%4];" \
        : "=r"(r0), "=r"(r1), "=r"(r2), "=r"(r3) : "r"(addr))

#define MMA_BF16(c, a, b)                                                     \
    asm volatile(                                                             \
        "mma.sync.aligned.m16n8k16.row.col.f32.bf16.bf16.f32 "                \
        "{%0,%1,%2,%3},{%4,%5,%6,%7},{%8,%9},{%0,%1,%2,%3};"                  \
        : "+f"((c)[0]), "+f"((c)[1]), "+f"((c)[2]), "+f"((c)[3])              \
        : "r"((a)[0]), "r"((a)[1]), "r"((a)[2]), "r"((a)[3]),                 \
          "r"((b)[0]), "r"((b)[1]))

// ---- bf16x2-split tensor-core GEMM (NT), CTA 128x64 (R13-proven) -----------
// g_gx[m][n] = A(m,:)·W(n,:) + bias[n];  Arow(m)=x[(b*T+t)*I], m=t*128+b, K=64
__global__ __launch_bounds__(256) void gemm_bf16x2(
    const float* __restrict__ A, const float* __restrict__ W,
    const float* __restrict__ bias, int K)
{
    __shared__ unsigned gsm[2*128*AKU*2 + 2*64*AKU*2];
    unsigned* sAh = gsm;
    unsigned* sAl = gsm + 2*128*AKU;
    unsigned* sBh = gsm + 4*128*AKU;
    unsigned* sBl = gsm + 4*128*AKU + 2*64*AKU;

    const int tid  = threadIdx.x;
    const int warp = tid >> 5, lane = tid & 31;
    const int gr   = lane >> 2, tg = lane & 3;
    const int wm   = warp & 3,  wn = warp >> 2;
    const int bm   = blockIdx.y, bn = blockIdx.x;

    int arow[4], ac4[4], brow[2], bc4[2];
    const float* asrc[4];
    const float* bsrc[2];
#pragma unroll
    for (int i = 0; i < 4; ++i) {
        const int idx = tid + (i << 8);
        arow[i] = idx >> 3; ac4[i] = idx & 7;
        asrc[i] = A + ((size_t)arow[i] * Tsz + bm) * Isz + (ac4[i] << 2);
    }
#pragma unroll
    for (int i = 0; i < 2; ++i) {
        const int idx = tid + (i << 8);
        brow[i] = idx >> 3; bc4[i] = idx & 7;
        bsrc[i] = W + ((size_t)(bn * 64 + brow[i])) * K + (bc4[i] << 2);
    }

    float c[2][4][4];
#pragma unroll
    for (int ms = 0; ms < 2; ++ms)
#pragma unroll
        for (int ns = 0; ns < 4; ++ns)
#pragma unroll
            for (int i = 0; i < 4; ++i) c[ms][ns][i] = 0.0f;

    const int lrow = lane & 15, lkh = lane >> 4;
    unsigned aAh = (unsigned)__cvta_generic_to_shared(sAh);
    unsigned aAl = (unsigned)__cvta_generic_to_shared(sAl);

    float4 ra[4], rb[2];
#pragma unroll
    for (int i = 0; i < 4; ++i) ra[i] = __ldg((const float4*)asrc[i]);
#pragma unroll
    for (int i = 0; i < 2; ++i) rb[i] = __ldg((const float4*)bsrc[i]);

    for (int kc = 0; kc < K; kc += 32) {
#pragma unroll
        for (int i = 0; i < 4; ++i) {
            const int ks = ac4[i] >> 2, pc = (ac4[i] & 3) << 1;
            const int di = ((ks << 7) + arow[i]) * AKU + pc;
            float r0, r1, r2, r3;
            sAh[di]     = pack2bf(ra[i].x, ra[i].y, r0, r1);
            sAh[di + 1] = pack2bf(ra[i].z, ra[i].w, r2, r3);
            sAl[di]     = pack2bf_only(r0, r1);
            sAl[di + 1] = pack2bf_only(r2, r3);
        }
#pragma unroll
        for (int i = 0; i < 2; ++i) {
            const int ks = bc4[i] >> 2, pc = (bc4[i] & 3) << 1;
            const int di = ((ks << 6) + brow[i]) * AKU + pc;
            float r0, r1, r2, r3;
            sBh[di]     = pack2bf(rb[i].x, rb[i].y, r0, r1);
            sBh[di + 1] = pack2bf(rb[i].z, rb[i].w, r2, r3);
            sBl[di]     = pack2bf_only(r0, r1);
            sBl[di + 1] = pack2bf_only(r2, r3);
        }
        __syncthreads();

        if (kc + 32 < K) {
#pragma unroll
            for (int i = 0; i < 4; ++i)
                ra[i] = __ldg((const float4*)(asrc[i] + kc + 32));
#pragma unroll
            for (int i = 0; i < 2; ++i)
                rb[i] = __ldg((const float4*)(bsrc[i] + kc + 32));
        }

#pragma unroll
        for (int ks = 0; ks < 2; ++ks) {
            unsigned Ah[2][4], Al[2][4];
#pragma unroll
            for (int ms = 0; ms < 2; ++ms) {
                const int rbase = wm * 32 + ms * 16;
                const unsigned off =
                    ((unsigned)(((ks << 7) + rbase + lrow) * AKU + (lkh << 2))) << 2;
                LDSM_X4(Ah[ms][0], Ah[ms][1], Ah[ms][2], Ah[ms][3], aAh + off);
                LDSM_X4(Al[ms][0], Al[ms][1], Al[ms][2], Al[ms][3], aAl + off);
            }
            unsigned Bh[4][2], Bl[4][2];
#pragma unroll
            for (int ns = 0; ns < 4; ++ns) {
                const int nrow = wn * 32 + ns * 8 + gr;
                const int di = ((ks << 6) + nrow) * AKU;
                Bh[ns][0] = sBh[di + tg];
                Bh[ns][1] = sBh[di + 4 + tg];
                Bl[ns][0] = sBl[di + tg];
                Bl[ns][1] = sBl[di + 4 + tg];
            }
#pragma unroll
            for (int ms = 0; ms < 2; ++ms)
#pragma unroll
                for (int ns = 0; ns < 4; ++ns)
                    MMA_BF16(c[ms][ns], Ah[ms], Bh[ns]);
#pragma unroll
            for (int ms = 0; ms < 2; ++ms)
#pragma unroll
                for (int ns = 0; ns < 4; ++ns)
                    MMA_BF16(c[ms][ns], Ah[ms], Bl[ns]);
#pragma unroll
            for (int ms = 0; ms < 2; ++ms)
#pragma unroll
                for (int ns = 0; ns < 4; ++ns)
                    MMA_BF16(c[ms][ns], Al[ms], Bh[ns]);
        }
        __syncthreads();
    }

#pragma unroll
    for (int ms = 0; ms < 2; ++ms) {
#pragma unroll
        for (int ns = 0; ns < 4; ++ns) {
            const int col = bn * 64 + wn * 32 + ns * 8 + tg * 2;
            const float b0 = __ldg(bias + col);
            const float b1 = __ldg(bias + col + 1);
            const size_t m0 = (size_t)bm * 128 + wm * 32 + ms * 16 + gr;
            float2 v0 = make_float2(c[ms][ns][0] + b0, c[ms][ns][1] + b1);
            float2 v1 = make_float2(c[ms][ns][2] + b0, c[ms][ns][3] + b1);
            *(float2*)(g_gx + m0 * Gsz + col)       = v0;
            *(float2*)(g_gx + (m0 + 8) * Gsz + col) = v1;
        }
    }
}

// ---- tensor-core GRU scan with DEFERRED fused next-layer input GEMM --------
// 128 CTAs = 8 bg x 16 hg; CTA tile: 16 batch x 16 hidden x 3 gates.
// Critical path per step: wait -> stage h -> recurrent MMA -> epilogue ->
// hnew store -> RELEASE. The fused gemm (gx_next[t-1] = y(t-1)·Wnext^T) runs
// AFTER the release, on the still-valid staged planes, consuming wait slack.
// gx tiles are CTA-private (same (b,j) set read & written) -> no cross-CTA
// hazard; post-fused __syncthreads orders fused LDSM reads before re-stage.
#define SP_STRIDE 49
#define SW_SLOT   52
#define SCAN3_WORDS (2*16*16*AKU + 256*SW_SLOT + 2*8*16*SP_STRIDE + 16*17)
#define SCAN3_BYTES (SCAN3_WORDS * 4)

__global__ __launch_bounds__(256, 1) void gru_scan_mma(
    const float* __restrict__ Whh, const float* __restrict__ bhh,
    const float* __restrict__ bih_extra, const float* __restrict__ Wnext,
    int layer, int fuse)
{
    extern __shared__ unsigned smu[];
    unsigned* sAh = smu;                          // [16 ks][16 row][12]
    unsigned* sAl = smu + 16*16*AKU;
    unsigned* sW  = smu + 2*16*16*AKU;            // [256 threads][52]
    float* sp     = (float*)(sW + 256*SW_SLOT);   // [8][16][49]
    float* sp2    = sp + 8*16*SP_STRIDE;          // [8][16][49]
    float* sHold  = sp2 + 8*16*SP_STRIDE;         // [16][17]

    const int tid  = threadIdx.x;
    const int warp = tid >> 5, lane = tid & 31;
    const int gr   = lane >> 2, tg = lane & 3;
    const int bg   = blockIdx.x >> 4;             // 0..7
    const int hg   = blockIdx.x & 15;             // 0..15
    const int b0   = bg << 4, j0 = hg << 4;
    const int bl   = tid >> 4;                    // epilogue batch 0..15
    const int jl   = tid & 15;                    // epilogue hidden 0..15

    // recurrent B fragments (weights) -> registers, once
    unsigned Bh[2][6][2], Bl[2][6][2];
#pragma unroll
    for (int s = 0; s < 2; ++s) {
#pragma unroll
        for (int ns = 0; ns < 6; ++ns) {
            const int n = ns * 8 + gr;
            const int g = n >> 4, jj = n & 15;
            const float* wr = Whh + (size_t)(g * 256 + j0 + jj) * 256;
            const int k0 = warp * 32 + s * 16 + tg * 2;
            float r0, r1;
            Bh[s][ns][0] = pack2bf(wr[k0],     wr[k0 + 1], r0, r1);
            Bl[s][ns][0] = pack2bf_only(r0, r1);
            Bh[s][ns][1] = pack2bf(wr[k0 + 8], wr[k0 + 9], r0, r1);
            Bl[s][ns][1] = pack2bf_only(r0, r1);
        }
    }
    // fused B fragments (W_ih next) -> smem, once
    if (fuse) {
        const int base = (warp * 32 + lane) * SW_SLOT;
#pragma unroll
        for (int s = 0; s < 2; ++s) {
#pragma unroll
            for (int ns = 0; ns < 6; ++ns) {
                const int n = ns * 8 + gr;
                const int g = n >> 4, jj = n & 15;
                const float* wr = Wnext + (size_t)(g * 256 + j0 + jj) * 256;
                const int k0 = warp * 32 + s * 16 + tg * 2;
                float r0, r1;
                unsigned h0 = pack2bf(wr[k0],     wr[k0 + 1], r0, r1);
                unsigned l0 = pack2bf_only(r0, r1);
                unsigned h1 = pack2bf(wr[k0 + 8], wr[k0 + 9], r0, r1);
                unsigned l1 = pack2bf_only(r0, r1);
                const int di = base + (s * 6 + ns) * 4;
                sW[di] = h0; sW[di + 1] = h1; sW[di + 2] = l0; sW[di + 3] = l1;
            }
        }
    }
    const float bhr = bhh[j0 + jl];
    const float bhz = bhh[256 + j0 + jl];
    const float bhn = bhh[512 + j0 + jl];
    // b_ih of THIS layer (when gx lacks it): r/z commute into the sums;
    // the n-component must stay OUTSIDE the r* factor (goes with gx_n).
    float bxr = 0.f, bxz = 0.f, bxn = 0.f;
    if (bih_extra) {
        bxr = bih_extra[j0 + jl];
        bxz = bih_extra[256 + j0 + jl];
        bxn = bih_extra[512 + j0 + jl];
    }
    unsigned* cnt = g_cnt + layer * (Tsz * 8);

    // gx prefetch (one (b,j) per thread, 3 gates)
    const float* gxp = g_gx + (size_t)(b0 + bl) * Gsz + j0 + jl;
    const size_t gxstep = (size_t)128 * Gsz;
    float gxr = __ldcg(gxp);
    float gxz = __ldcg(gxp + 256);
    float gxn = __ldcg(gxp + 512);

    const int lrow = lane & 15, lkh = lane >> 4;
    const unsigned aAh = (unsigned)__cvta_generic_to_shared(sAh);
    const unsigned aAl = (unsigned)__cvta_generic_to_shared(sAl);
    const int swbase = (warp * 32 + lane) * SW_SLOT;

    const int tEnd = Tsz + (fuse ? 1 : 0);
    int cur = 0;
    for (int t = 0; t < tEnd; ++t) {
        if (t > 0) {
            const unsigned* c = cnt + ((t - 1) << 3) + bg;
            unsigned v;
            do {
                asm volatile("ld.acquire.gpu.global.u32 %0, [%1];"
                             : "=r"(v) : "l"(c) : "memory");
            } while (v < 16u);
        }
        // stage h: 16 rows x 256 -> bf16 hi/lo planes (ldmatrix layout)
        const float* hsrc = g_hbuf + cur * (Bsz * Hsz) + (b0 << 8);
#pragma unroll
        for (int r = 0; r < 4; ++r) {
            const int idx = tid + (r << 8);
            const int row = idx >> 6, f4 = idx & 63;
            float4 v = __ldcg((const float4*)(hsrc + (row << 8)) + f4);
            const int ks = f4 >> 2, pc = (f4 & 3) << 1;
            const int di = ((ks << 4) + row) * AKU + pc;
            float r0, r1, r2, r3;
            sAh[di]     = pack2bf(v.x, v.y, r0, r1);
            sAh[di + 1] = pack2bf(v.z, v.w, r2, r3);
            sAl[di]     = pack2bf_only(r0, r1);
            sAl[di + 1] = pack2bf_only(r2, r3);
        }
        sHold[bl * 17 + jl] = __ldcg(hsrc + (bl << 8) + j0 + jl);
        __syncthreads();

        // ---- critical path: recurrent MMA + epilogue + release -------------
        if (t < Tsz) {
            float c[6][4];
#pragma unroll
            for (int ns = 0; ns < 6; ++ns)
#pragma unroll
                for (int i = 0; i < 4; ++i) c[ns][i] = 0.0f;

#pragma unroll
            for (int s = 0; s < 2; ++s) {
                const int ksg = warp * 2 + s;
                const unsigned off =
                    ((unsigned)(((ksg << 4) + lrow) * AKU + (lkh << 2))) << 2;
                unsigned Ah[4], Al[4];
                LDSM_X4(Ah[0], Ah[1], Ah[2], Ah[3], aAh + off);
                LDSM_X4(Al[0], Al[1], Al[2], Al[3], aAl + off);
#pragma unroll
                for (int ns = 0; ns < 6; ++ns) MMA_BF16(c[ns], Ah, Bh[s][ns]);
#pragma unroll
                for (int ns = 0; ns < 6; ++ns) MMA_BF16(c[ns], Ah, Bl[s][ns]);
#pragma unroll
                for (int ns = 0; ns < 6; ++ns) MMA_BF16(c[ns], Al, Bh[s][ns]);
            }
            float* spw = sp + warp * (16 * SP_STRIDE);
#pragma unroll
            for (int ns = 0; ns < 6; ++ns) {
                const int n = ns * 8 + tg * 2;
                spw[gr * SP_STRIDE + n]           = c[ns][0];
                spw[gr * SP_STRIDE + n + 1]       = c[ns][1];
                spw[(gr + 8) * SP_STRIDE + n]     = c[ns][2];
                spw[(gr + 8) * SP_STRIDE + n + 1] = c[ns][3];
            }
            __syncthreads();

            float ar = bhr + bxr + gxr, az = bhz + bxz + gxz, an = bhn;
#pragma unroll
            for (int w8 = 0; w8 < 8; ++w8) {
                const float* q = sp + w8 * (16 * SP_STRIDE) + bl * SP_STRIDE;
                ar += q[jl];
                az += q[16 + jl];
                an += q[32 + jl];
            }
            const float r = __fdividef(1.0f, 1.0f + __expf(-ar));
            const float z = __fdividef(1.0f, 1.0f + __expf(-az));
            const float xn = fmaf(r, an, gxn + bxn);   // b_ih_n outside r*
            const float e = __expf(2.0f * fabsf(xn));
            float n = 1.0f - __fdividef(2.0f, e + 1.0f);
            n = copysignf(n, xn);

            const float hold = sHold[bl * 17 + jl];
            const float hnew = fmaf(z, hold - n, n);   // (1-z)*n + z*h

            __stcg(g_hbuf + (cur ^ 1) * (Bsz * Hsz) + ((b0 + bl) << 8) + j0 + jl,
                   hnew);

            if (t + 1 < Tsz) {
                const float* p = gxp + (size_t)(t + 1) * gxstep;
                gxr = __ldcg(p);
                gxz = __ldcg(p + 256);
                gxn = __ldcg(p + 512);
            }
            __syncthreads();   // all hnew stores issued CTA-wide
            if (((t + 1 < Tsz) || fuse) && tid == 0) {
                asm volatile("red.release.gpu.global.add.u32 [%0], 1;"
                             :: "l"(cnt + (t << 3) + bg) : "memory");
            }
        }

        // ---- deferred (off critical path): fused gemm on staged y(t-1) -----
        if (fuse && t >= 1) {
            float c2[6][4];
#pragma unroll
            for (int ns = 0; ns < 6; ++ns)
#pragma unroll
                for (int i = 0; i < 4; ++i) c2[ns][i] = 0.0f;

#pragma unroll
            for (int s = 0; s < 2; ++s) {
                const int ksg = warp * 2 + s;
                const unsigned off =
                    ((unsigned)(((ksg << 4) + lrow) * AKU + (lkh << 2))) << 2;
                unsigned Ah[4], Al[4];
                LDSM_X4(Ah[0], Ah[1], Ah[2], Ah[3], aAh + off);
                LDSM_X4(Al[0], Al[1], Al[2], Al[3], aAl + off);
#pragma unroll
                for (int ns = 0; ns < 6; ++ns) {
                    const uint4 q = *(const uint4*)(sW + swbase + (s * 6 + ns) * 4);
                    unsigned bh2[2] = {q.x, q.y};
                    unsigned bl2[2] = {q.z, q.w};
                    MMA_BF16(c2[ns], Ah, bh2);
                    MMA_BF16(c2[ns], Ah, bl2);
                    MMA_BF16(c2[ns], Al, bh2);
                }
            }
            float* spw2 = sp2 + warp * (16 * SP_STRIDE);
#pragma unroll
            for (int ns = 0; ns < 6; ++ns) {
                const int n = ns * 8 + tg * 2;
                spw2[gr * SP_STRIDE + n]           = c2[ns][0];
                spw2[gr * SP_STRIDE + n + 1]       = c2[ns][1];
                spw2[(gr + 8) * SP_STRIDE + n]     = c2[ns][2];
                spw2[(gr + 8) * SP_STRIDE + n + 1] = c2[ns][3];
            }
            __syncthreads();   // also orders fused LDSM reads before re-stage

            float ar2 = 0.f, az2 = 0.f, an2 = 0.f;
#pragma unroll
            for (int w8 = 0; w8 < 8; ++w8) {
                const float* q = sp2 + w8 * (16 * SP_STRIDE) + bl * SP_STRIDE;
                ar2 += q[jl];
                az2 += q[16 + jl];
                an2 += q[32 + jl];
            }
            float* gdst = g_gx + ((size_t)(((t - 1) << 7) + b0 + bl)) * Gsz
                          + j0 + jl;
            __stcg(gdst,       ar2);
            __stcg(gdst + 256, az2);
            __stcg(gdst + 512, an2);
        } else {
            __syncthreads();   // keep re-stage ordering when no fused section
        }

        cur ^= 1;
    }
}

// ---- head: out[b] = W2 . relu(W1 . h_last[b] + b1) + b2 --------------------
__global__ void head_kernel(const float* __restrict__ W1, const float* __restrict__ b1,
                            const float* __restrict__ W2, const float* __restrict__ b2,
                            float* __restrict__ out)
{
    __shared__ float red[128];
    const int b = blockIdx.x, u = threadIdx.x;
    const float* hb = g_hbuf + (b << 8);
    const float* w  = W1 + (size_t)u * 256;

    float acc = b1[u];
#pragma unroll 8
    for (int k4 = 0; k4 < 64; ++k4) {
        const float4 h4 = __ldcg((const float4*)hb + k4);
        const float4 w4 = __ldg((const float4*)w + k4);
        acc = fmaf(h4.x, w4.x, acc); acc = fmaf(h4.y, w4.y, acc);
        acc = fmaf(h4.z, w4.z, acc); acc = fmaf(h4.w, w4.w, acc);
    }
    red[u] = fmaxf(acc, 0.0f) * __ldg(W2 + u);
    __syncthreads();
#pragma unroll
    for (int s = 64; s > 0; s >>= 1) {
        if (u < s) red[u] += red[u + s];
        __syncthreads();
    }
    if (u == 0) out[b] = red[0] + b2[0];
}

// ---- launch sequence (graph-capturable: kernel launches only) --------------
extern "C" void kernel_launch(void* const* d_in, const int* in_sizes, int n_in,
                              void* d_out, int out_size)
{
    const float* x    = (const float*)d_in[0];
    const float* Wih0 = (const float*)d_in[1];
    const float* Whh0 = (const float*)d_in[2];
    const float* bih0 = (const float*)d_in[3];
    const float* bhh0 = (const float*)d_in[4];
    const float* Wih1 = (const float*)d_in[5];
    const float* Whh1 = (const float*)d_in[6];
    const float* bih1 = (const float*)d_in[7];
    const float* bhh1 = (const float*)d_in[8];
    const float* W1   = (const float*)d_in[9];
    const float* b1   = (const float*)d_in[10];
    const float* W2   = (const float*)d_in[11];
    const float* b2   = (const float*)d_in[12];
    float* out = (float*)d_out;

    cudaFuncSetAttribute(gru_scan_mma, cudaFuncAttributeMaxDynamicSharedMemorySize,
                         SCAN3_BYTES);

    const dim3 ggrid(12, 512);

    // fresh state + barrier counters every replay
    zero_state<<<64, 256>>>(1);

    // layer 0: input GEMM, then scan with deferred fused layer-1 input GEMM
    gemm_bf16x2<<<ggrid, 256>>>(x, Wih0, bih0, Isz);
    gru_scan_mma<<<128, 256, SCAN3_BYTES>>>(Whh0, bhh0, nullptr, Wih1, 0, 1);

    // layer 1: re-zero hidden state, scan (gx in g_gx lacks bih1 -> bih_extra)
    zero_state<<<64, 256>>>(0);
    gru_scan_mma<<<128, 256, SCAN3_BYTES>>>(Whh1, bhh1, bih1, nullptr, 1, 0);

    // head
    head_kernel<<<128, 128>>>(W1, b1, W2, b2, out);
}